// round 10
// baseline (speedup 1.0000x reference)
#include <cuda_runtime.h>
#include <cstdint>

// out[b,t,a] = start_state[b,a] + (t/255) * patterns[iid[b], t, a]
// B=256, T=256, AD=64 -> each (b,t) row = 64 floats = 8 x 256-bit vectors.
//
// R10: 256-bit LDG/STG (sm_100+), 4 items per thread (128B in flight/thread),
// 512 CTAs x 256 threads. Lowest dynamic-instruction-count realization:
// iid/start_state/addressing amortized over 4 v8 items.

#define B_   256
#define T_   256
#define AD_  64
#define TPB  256
#define ITEMS 4                 // v8 items per thread
#define CHUNKS_PER_B 2          // 256 t / (32 trows * 4 items)

struct f8 { float v[8]; };

__device__ __forceinline__ f8 ldg_v8(const float* p) {
    f8 r;
    asm volatile("ld.global.nc.v8.f32 {%0,%1,%2,%3,%4,%5,%6,%7}, [%8];"
                 : "=f"(r.v[0]), "=f"(r.v[1]), "=f"(r.v[2]), "=f"(r.v[3]),
                   "=f"(r.v[4]), "=f"(r.v[5]), "=f"(r.v[6]), "=f"(r.v[7])
                 : "l"(p));
    return r;
}

__device__ __forceinline__ void stg_v8(float* p, const f8& r) {
    asm volatile("st.global.v8.f32 [%0], {%1,%2,%3,%4,%5,%6,%7,%8};"
                 :: "l"(p),
                    "f"(r.v[0]), "f"(r.v[1]), "f"(r.v[2]), "f"(r.v[3]),
                    "f"(r.v[4]), "f"(r.v[5]), "f"(r.v[6]), "f"(r.v[7])
                 : "memory");
}

__global__ __launch_bounds__(TPB)
void traj_kernel(const float* __restrict__ start_state,    // [B, 64]
                 const int*   __restrict__ instruction_id, // [B]
                 const float* __restrict__ patterns,       // [V, T, 64]
                 float*       __restrict__ out)            // [B, T, 64]
{
    const unsigned bid   = blockIdx.x;
    const unsigned b     = bid >> 1;           // 2 chunks of 128 t per batch row
    const unsigned chunk = bid & 1u;
    const unsigned tid   = threadIdx.x;
    const unsigned a8    = tid & 7u;           // 256-bit slot within 64-float row
    const unsigned trow  = tid >> 3;           // 0..31
    const unsigned tbase = chunk * 128u;       // chunk covers 128 t values

    const int iid = __ldg(&instruction_id[b]);

    const f8 s = ldg_v8(start_state + (size_t)b * AD_ + a8 * 8u);

    const float* __restrict__ pat =
        patterns + ((size_t)iid * T_ + tbase) * AD_ + a8 * 8u;
    float* __restrict__ dst =
        out + ((size_t)b * T_ + tbase) * AD_ + a8 * 8u;

    // 4 independent 256-bit loads, front-batched (t stride 32 within chunk).
    f8 p[ITEMS];
#pragma unroll
    for (int i = 0; i < ITEMS; i++)
        p[i] = ldg_v8(pat + (size_t)(trow + i * 32u) * AD_);

#pragma unroll
    for (int i = 0; i < ITEMS; i++) {
        const unsigned tl = trow + (unsigned)i * 32u;
        const float prog = (float)(tbase + tl) * (1.0f / (float)(T_ - 1));
        f8 r;
#pragma unroll
        for (int k = 0; k < 8; k++) r.v[k] = fmaf(prog, p[i].v[k], s.v[k]);
        stg_v8(dst + (size_t)tl * AD_, r);
    }
}

extern "C" void kernel_launch(void* const* d_in, const int* in_sizes, int n_in,
                              void* d_out, int out_size)
{
    const float* start_state    = (const float*)d_in[0];
    const int*   instruction_id = (const int*)  d_in[1];
    const float* patterns       = (const float*)d_in[27];
    float*       out            = (float*)d_out;

    traj_kernel<<<B_ * CHUNKS_PER_B, TPB>>>(start_state, instruction_id, patterns, out);
}